// round 10
// baseline (speedup 1.0000x reference)
#include <cuda_runtime.h>
#include <cuda_fp16.h>
#include <cstdint>
#include <math.h>

// Problem constants: B=16, S=2048, D=512, H=512, K=2
#define Bq 16
#define Sq 2048
#define Dq 512
#define Hq 512
#define Mq (Bq * Sq)      // 32768
#define Nq (3 * Hq)       // 1536
#define Kq (2 * Dq)       // 1024

// Scan chunking
#define NC 32
#define ST (Sq / NC)      // 64
#define CH (Bq * Hq)      // 8192

// ---------------------------------------------------------------------------
// Device-global scratch (no allocations allowed)
// ---------------------------------------------------------------------------
__device__ __half g_xh[(size_t)Mq * Dq];           // x fp16         32MB
__device__ __half g_wh[(size_t)Nq * Kq];           // w fp16          3MB
__device__ __half g_z16[(size_t)Mq * Hq];          // tanh(Z) fp16   32MB
__device__ __half g_f16[(size_t)Mq * Hq];          // sig(F) fp16    32MB
__device__ __half g_o16[(size_t)Mq * Hq];          // sig(O) fp16    32MB
__device__ float g_P[NC * CH];                     // chunk f-products
__device__ float g_r[NC * CH];                     // chunk zero-state c

// ---------------------------------------------------------------------------
// Helpers
// ---------------------------------------------------------------------------
__device__ __forceinline__ uint32_t smem_u32(const void* p) {
    uint32_t a;
    asm("{ .reg .u64 t; cvta.to.shared.u64 t, %1; cvt.u32.u64 %0, t; }"
        : "=r"(a) : "l"(p));
    return a;
}

__device__ __forceinline__ void ldsm_x4(uint32_t& r0, uint32_t& r1,
                                        uint32_t& r2, uint32_t& r3,
                                        uint32_t addr) {
    asm volatile("ldmatrix.sync.aligned.m8n8.x4.shared.b16 {%0,%1,%2,%3}, [%4];"
                 : "=r"(r0), "=r"(r1), "=r"(r2), "=r"(r3) : "r"(addr));
}

__device__ __forceinline__ void mma_f16(float& d0, float& d1, float& d2, float& d3,
                                        uint32_t a0, uint32_t a1, uint32_t a2, uint32_t a3,
                                        uint32_t b0, uint32_t b1) {
    asm volatile("mma.sync.aligned.m16n8k16.row.col.f32.f16.f16.f32 "
                 "{%0,%1,%2,%3}, {%4,%5,%6,%7}, {%8,%9}, {%0,%1,%2,%3};"
                 : "+f"(d0), "+f"(d1), "+f"(d2), "+f"(d3)
                 : "r"(a0), "r"(a1), "r"(a2), "r"(a3), "r"(b0), "r"(b1));
}

// 16B async copy; src_sz = 16 (copy) or 0 (zero-fill; src must still be valid)
__device__ __forceinline__ void cp16(uint32_t dst, const void* src, int src_sz) {
    asm volatile("cp.async.cg.shared.global [%0], [%1], 16, %2;"
                 :: "r"(dst), "l"(src), "r"(src_sz));
}
#define CP_COMMIT() asm volatile("cp.async.commit_group;" ::: "memory")
#define CP_WAIT(n)  asm volatile("cp.async.wait_group %0;" :: "n"(n) : "memory")

// ---------------------------------------------------------------------------
// Kernel 1: fused prep.
//  blocks [0, 16384):  x fp32 -> fp16 (float4-vectorized)
//  blocks [16384, 22528): w [n][d][tap] -> fp16 [n][k], k=tap*512+d
// ---------------------------------------------------------------------------
#define XPREP_BLOCKS (Mq * Dq / 4 / 256)          // 16384
#define WPREP_BLOCKS (Nq * Kq / 256)              // 6144

__global__ void prep_fused(const float* __restrict__ x,
                           const float* __restrict__ conv_w) {
    if (blockIdx.x < XPREP_BLOCKS) {
        size_t i = (size_t)blockIdx.x * 256 + threadIdx.x;   // float4 index
        float4 v = reinterpret_cast<const float4*>(x)[i];
        __half2* ph = reinterpret_cast<__half2*>(g_xh);
        ph[i * 2 + 0] = __floats2half2_rn(v.x, v.y);
        ph[i * 2 + 1] = __floats2half2_rn(v.z, v.w);
    } else {
        int idx = (blockIdx.x - XPREP_BLOCKS) * 256 + threadIdx.x;
        int n = idx >> 10;
        int k = idx & 1023;
        int tap = k >> 9;
        int d = k & 511;
        g_wh[idx] = __float2half_rn(conv_w[(size_t)n * 1024 + (d << 1) + tap]);
    }
}

// ---------------------------------------------------------------------------
// Kernel 2: mma.sync fp16 single-pass GEMM, warp tile 64x64.
// CTA tile 128x128, BK=64, 128 threads (4 warps as 2m x 2n), 3-stage
// cp.async pipeline (3 x 32KB), 2 CTAs/SM.
//   A[m,k]: k<512 -> xh[m-1][k] (0 at t==0); k>=512 -> xh[m][k-512]
// Stage: A | B, each 128 rows x 128B, chunk-XOR swizzled.
// Per warp per k16-step: 8 LDSM.x4 + 32 HMMA into 32 independent
// accumulators (LDSM:HMMA = 1:4, no RAW chains).
// Epilogue: bias + activation -> planar fp16 g_z16/g_f16/g_o16.
// ---------------------------------------------------------------------------
#define T_A  0
#define T_B  16384
#define STAGE_BYTES 32768
#define GEMM_SMEM (3 * STAGE_BYTES)     // 96KB -> 2 CTAs/SM

__global__ __launch_bounds__(128, 2)
void gemm_mma(const float* __restrict__ bias) {
    extern __shared__ char smem[];
    const uint32_t sb = smem_u32(smem);
    const int tid = threadIdx.x;
    const int lane = tid & 31;
    const int wrp = tid >> 5;
    const int wm = wrp & 1;          // m-warp 0..1  (64 rows each)
    const int wn = wrp >> 1;         // n-warp 0..1  (64 cols each)
    const int n0 = blockIdx.x * 128;
    const int m0 = blockIdx.y * 128;

    float acc[4][8][4];
#pragma unroll
    for (int mt = 0; mt < 4; mt++)
#pragma unroll
        for (int nt = 0; nt < 8; nt++)
#pragma unroll
            for (int r = 0; r < 4; r++) acc[mt][nt][r] = 0.0f;

    // --- loader geometry: 1 thread/row, 8 16B-chunks each, 2 tiles ---
    const int lrow = tid;            // 0..127

    // --- ldmatrix address components ---
    const int xorv = lane & 7;
    const int hvA = lane >> 4;
    const int hvB = (lane >> 3) & 1;
    uint32_t arow[4];
#pragma unroll
    for (int mt = 0; mt < 4; mt++)
        arow[mt] = (uint32_t)(wm * 64 + mt * 16 + (lane & 15)) * 128;
    uint32_t brow[4];
#pragma unroll
    for (int g2 = 0; g2 < 4; g2++)
        brow[g2] = (uint32_t)(wn * 64 + g2 * 16 + (lane & 7) + ((lane >> 4) & 1) * 8) * 128;

    auto load_stage = [&](int kc, int buf) {
        const uint32_t base = sb + buf * STAGE_BYTES;
        const int tap = kc >> 3;
        const int kb = (kc & 7) * 64;
        const int m = m0 + lrow;
        const bool ok = (tap == 1) || ((m & (Sq - 1)) != 0);
        const size_t amrow = (size_t)(ok && tap == 0 ? m - 1 : m) * Dq + kb;
        const int asz = ok ? 16 : 0;
        const size_t brow_g = (size_t)(n0 + lrow) * Kq + kc * 64;
#pragma unroll
        for (int c = 0; c < 8; c++) {
            const uint32_t dsto = (uint32_t)lrow * 128 +
                                  (uint32_t)((c ^ (lrow & 7)) * 16);
            cp16(base + T_A + dsto, g_xh + amrow + c * 8, asz);
            cp16(base + T_B + dsto, g_wh + brow_g + c * 8, 16);
        }
        CP_COMMIT();
    };

    load_stage(0, 0);
    load_stage(1, 1);

    int buf = 0, nbuf2 = 2;   // buf = kc%3 ; nbuf2 = (kc+2)%3

    for (int kc = 0; kc < 16; kc++) {
        const uint32_t base = sb + buf * STAGE_BYTES;

        if (kc < 15) { CP_WAIT(1); } else { CP_WAIT(0); }
        __syncthreads();

        if (kc + 2 < 16) load_stage(kc + 2, nbuf2);

        // ---- compute: 4 k16 steps; 8 LDSM + 32 HMMA each ----
#pragma unroll
        for (int s = 0; s < 4; s++) {
            const uint32_t achunk = (uint32_t)(((s * 2 + hvA) ^ xorv) * 16);
            const uint32_t bchunk = (uint32_t)(((s * 2 + hvB) ^ xorv) * 16);

            uint32_t ah[4][4];
#pragma unroll
            for (int mt = 0; mt < 4; mt++)
                ldsm_x4(ah[mt][0], ah[mt][1], ah[mt][2], ah[mt][3],
                        base + T_A + arow[mt] + achunk);
            uint32_t bh[8][2];
#pragma unroll
            for (int g2 = 0; g2 < 4; g2++)
                ldsm_x4(bh[g2 * 2][0], bh[g2 * 2][1], bh[g2 * 2 + 1][0], bh[g2 * 2 + 1][1],
                        base + T_B + brow[g2] + bchunk);
#pragma unroll
            for (int mt = 0; mt < 4; mt++)
#pragma unroll
                for (int nt = 0; nt < 8; nt++)
                    mma_f16(acc[mt][nt][0], acc[mt][nt][1], acc[mt][nt][2], acc[mt][nt][3],
                            ah[mt][0], ah[mt][1], ah[mt][2], ah[mt][3],
                            bh[nt][0], bh[nt][1]);
        }

        buf = (buf == 2) ? 0 : buf + 1;
        nbuf2 = (nbuf2 == 2) ? 0 : nbuf2 + 1;
    }

    // ---- epilogue: bias + activation -> planar fp16 g_z16/g_f16/g_o16 ----
    const int sec = n0 >> 9;                 // 0=Z(tanh) 1=F(sig) 2=O(sig)
    __half* dst = (sec == 0) ? g_z16 : ((sec == 1) ? g_f16 : g_o16);
    const int colsec = (n0 & 511) + wn * 64;
    const int g = lane >> 2;
    const int tg = lane & 3;

#pragma unroll
    for (int mt = 0; mt < 4; mt++) {
        const int row0 = m0 + wm * 64 + mt * 16 + g;
#pragma unroll
        for (int nt = 0; nt < 8; nt++) {
            const int col = colsec + nt * 8 + tg * 2;
            const float b0 = bias[n0 + wn * 64 + nt * 8 + tg * 2];
            const float b1 = bias[n0 + wn * 64 + nt * 8 + tg * 2 + 1];
            float v0 = acc[mt][nt][0] + b0;
            float v1 = acc[mt][nt][1] + b1;
            float v2 = acc[mt][nt][2] + b0;
            float v3 = acc[mt][nt][3] + b1;
            if (sec == 0) {
                v0 = tanhf(v0); v1 = tanhf(v1); v2 = tanhf(v2); v3 = tanhf(v3);
            } else {
                v0 = 1.0f / (1.0f + __expf(-v0));
                v1 = 1.0f / (1.0f + __expf(-v1));
                v2 = 1.0f / (1.0f + __expf(-v2));
                v3 = 1.0f / (1.0f + __expf(-v3));
            }
            *reinterpret_cast<__half2*>(&dst[(size_t)row0 * Hq + col]) =
                __floats2half2_rn(v0, v1);
            *reinterpret_cast<__half2*>(&dst[(size_t)(row0 + 8) * Hq + col]) =
                __floats2half2_rn(v2, v3);
        }
    }
}

// ---------------------------------------------------------------------------
// Kernel 3: scan phase A — per-(chain-pair, chunk) affine summary (P, r).
// 131072 threads, 2 chains (adjacent h) per thread via half2 loads.
// ---------------------------------------------------------------------------
__global__ void scanA_kernel() {
    const int gid = blockIdx.x * blockDim.x + threadIdx.x;
    if (gid >= (CH / 2) * NC) return;
    const int hp = gid & 255;                // h-pair index: h = 2hp, 2hp+1
    const int j = (gid >> 8) & (NC - 1);
    const int b = gid >> 13;

    const __half2* z2 = reinterpret_cast<const __half2*>(g_z16);
    const __half2* f2 = reinterpret_cast<const __half2*>(g_f16);
    size_t hidx = (((size_t)b * Sq + j * ST) * Hq + hp * 2) >> 1;

    float2 P = make_float2(1.0f, 1.0f);
    float2 r = make_float2(0.0f, 0.0f);
#pragma unroll 4
    for (int t = 0; t < ST; t++, hidx += Hq / 2) {
        const float2 z = __half22float2(z2[hidx]);
        const float2 f = __half22float2(f2[hidx]);
        r.x = fmaf(f.x, r.x - z.x, z.x);
        r.y = fmaf(f.y, r.y - z.y, z.y);
        P.x *= f.x;
        P.y *= f.y;
    }
    const int chain2 = b * Hq + hp * 2;
    *reinterpret_cast<float2*>(&g_P[j * CH + chain2]) = P;
    *reinterpret_cast<float2*>(&g_r[j * CH + chain2]) = r;
}

// ---------------------------------------------------------------------------
// Kernel 4: scan phase B — fold upstream summaries, replay local recurrence.
// 2 chains per thread. out = [C (B,S,H)] | [Hout (B,S,H)], fp32.
// ---------------------------------------------------------------------------
__global__ void scanB_kernel(float* __restrict__ out) {
    const int gid = blockIdx.x * blockDim.x + threadIdx.x;
    if (gid >= (CH / 2) * NC) return;
    const int hp = gid & 255;
    const int j = (gid >> 8) & (NC - 1);
    const int b = gid >> 13;
    const int chain2 = b * Hq + hp * 2;

    float2 c = make_float2(0.0f, 0.0f);
    for (int jj = 0; jj < j; jj++) {
        const float2 P = *reinterpret_cast<const float2*>(&g_P[jj * CH + chain2]);
        const float2 r = *reinterpret_cast<const float2*>(&g_r[jj * CH + chain2]);
        c.x = fmaf(P.x, c.x, r.x);
        c.y = fmaf(P.y, c.y, r.y);
    }

    const __half2* z2 = reinterpret_cast<const __half2*>(g_z16);
    const __half2* f2 = reinterpret_cast<const __half2*>(g_f16);
    const __half2* o2 = reinterpret_cast<const __half2*>(g_o16);
    float* Cout = out;
    float* Hout = out + (size_t)Mq * Hq;

    size_t idx = ((size_t)b * Sq + j * ST) * Hq + hp * 2;   // fp32 elem index
#pragma unroll 4
    for (int t = 0; t < ST; t++, idx += Hq) {
        const float2 z = __half22float2(z2[idx >> 1]);
        const float2 f = __half22float2(f2[idx >> 1]);
        const float2 o = __half22float2(o2[idx >> 1]);
        c.x = fmaf(f.x, c.x - z.x, z.x);
        c.y = fmaf(f.y, c.y - z.y, z.y);
        *reinterpret_cast<float2*>(&Cout[idx]) = c;
        *reinterpret_cast<float2*>(&Hout[idx]) = make_float2(o.x * c.x, o.y * c.y);
    }
}

// ---------------------------------------------------------------------------
// Launch
// ---------------------------------------------------------------------------
extern "C" void kernel_launch(void* const* d_in, const int* in_sizes, int n_in,
                              void* d_out, int out_size) {
    const float* x      = (const float*)d_in[0];  // [B, S, D]
    const float* conv_w = (const float*)d_in[1];  // [3H, D, 2]
    const float* conv_b = (const float*)d_in[2];  // [3H]
    float* out = (float*)d_out;                   // [C | Hout]
    (void)in_sizes; (void)n_in; (void)out_size;

    prep_fused<<<XPREP_BLOCKS + WPREP_BLOCKS, 256>>>(x, conv_w);

    cudaFuncSetAttribute(gemm_mma, cudaFuncAttributeMaxDynamicSharedMemorySize,
                         GEMM_SMEM);
    {
        dim3 grid(Nq / 128, Mq / 128);   // (12, 256); n fastest -> A L2 reuse
        gemm_mma<<<grid, 128, GEMM_SMEM>>>(conv_b);
    }

    scanA_kernel<<<(CH / 2) * NC / 256, 256>>>();
    scanB_kernel<<<(CH / 2) * NC / 256, 256>>>(out);
}

// round 13
// speedup vs baseline: 1.4257x; 1.4257x over previous
#include <cuda_runtime.h>
#include <cuda_fp16.h>
#include <cstdint>
#include <math.h>

// Problem constants: B=16, S=2048, D=512, H=512, K=2
#define Bq 16
#define Sq 2048
#define Dq 512
#define Hq 512
#define Mq (Bq * Sq)      // 32768
#define Nq (3 * Hq)       // 1536
#define Kq (2 * Dq)       // 1024

// Scan chunking
#define NC 64
#define ST (Sq / NC)      // 32
#define CH (Bq * Hq)      // 8192

// ---------------------------------------------------------------------------
// Device-global scratch (no allocations allowed)
// ---------------------------------------------------------------------------
__device__ __half g_xh[(size_t)Mq * Dq];           // x fp16         32MB
__device__ __half g_wh[(size_t)Nq * Kq];           // w fp16          3MB
__device__ __half g_z16[(size_t)Mq * Hq];          // tanh(Z) fp16   32MB
__device__ __half g_f16[(size_t)Mq * Hq];          // sig(F) fp16    32MB
__device__ __half g_o16[(size_t)Mq * Hq];          // sig(O) fp16    32MB
__device__ float g_P[NC * CH];                     // chunk f-products 2MB
__device__ float g_r[NC * CH];                     // chunk zero-state c 2MB

// ---------------------------------------------------------------------------
// Helpers
// ---------------------------------------------------------------------------
__device__ __forceinline__ uint32_t smem_u32(const void* p) {
    uint32_t a;
    asm("{ .reg .u64 t; cvta.to.shared.u64 t, %1; cvt.u32.u64 %0, t; }"
        : "=r"(a) : "l"(p));
    return a;
}

__device__ __forceinline__ void ldsm_x4(uint32_t& r0, uint32_t& r1,
                                        uint32_t& r2, uint32_t& r3,
                                        uint32_t addr) {
    asm volatile("ldmatrix.sync.aligned.m8n8.x4.shared.b16 {%0,%1,%2,%3}, [%4];"
                 : "=r"(r0), "=r"(r1), "=r"(r2), "=r"(r3) : "r"(addr));
}

__device__ __forceinline__ void mma_f16(float& d0, float& d1, float& d2, float& d3,
                                        uint32_t a0, uint32_t a1, uint32_t a2, uint32_t a3,
                                        uint32_t b0, uint32_t b1) {
    asm volatile("mma.sync.aligned.m16n8k16.row.col.f32.f16.f16.f32 "
                 "{%0,%1,%2,%3}, {%4,%5,%6,%7}, {%8,%9}, {%0,%1,%2,%3};"
                 : "+f"(d0), "+f"(d1), "+f"(d2), "+f"(d3)
                 : "r"(a0), "r"(a1), "r"(a2), "r"(a3), "r"(b0), "r"(b1));
}

// 16B async copy; src_sz = 16 (copy) or 0 (zero-fill; src must still be valid)
__device__ __forceinline__ void cp16(uint32_t dst, const void* src, int src_sz) {
    asm volatile("cp.async.cg.shared.global [%0], [%1], 16, %2;"
                 :: "r"(dst), "l"(src), "r"(src_sz));
}
#define CP_COMMIT() asm volatile("cp.async.commit_group;" ::: "memory")
#define CP_WAIT(n)  asm volatile("cp.async.wait_group %0;" :: "n"(n) : "memory")

// ---------------------------------------------------------------------------
// Kernel 1: fused prep.
//  blocks [0, 16384):  x fp32 -> fp16 (float4-vectorized)
//  blocks [16384, 22528): w [n][d][tap] -> fp16 [n][k], k=tap*512+d
// ---------------------------------------------------------------------------
#define XPREP_BLOCKS (Mq * Dq / 4 / 256)          // 16384
#define WPREP_BLOCKS (Nq * Kq / 256)              // 6144

__global__ void prep_fused(const float* __restrict__ x,
                           const float* __restrict__ conv_w) {
    if (blockIdx.x < XPREP_BLOCKS) {
        size_t i = (size_t)blockIdx.x * 256 + threadIdx.x;   // float4 index
        float4 v = reinterpret_cast<const float4*>(x)[i];
        __half2* ph = reinterpret_cast<__half2*>(g_xh);
        ph[i * 2 + 0] = __floats2half2_rn(v.x, v.y);
        ph[i * 2 + 1] = __floats2half2_rn(v.z, v.w);
    } else {
        int idx = (blockIdx.x - XPREP_BLOCKS) * 256 + threadIdx.x;
        int n = idx >> 10;
        int k = idx & 1023;
        int tap = k >> 9;
        int d = k & 511;
        g_wh[idx] = __float2half_rn(conv_w[(size_t)n * 1024 + (d << 1) + tap]);
    }
}

// ---------------------------------------------------------------------------
// Kernel 2 (R8 configuration — at the legacy-HMMA issue floor, do not touch):
// mma.sync fp16 single-pass GEMM. CTA tile 128x128, BK=64, 256 threads
// (8 warps as 4m x 2n, warp tile 32x64), 3-stage cp.async pipeline
// (3 x 32KB), single barrier per chunk, 2 CTAs/SM (4 warps/SMSP).
//   A[m,k]: k<512 -> xh[m-1][k] (0 at t==0); k>=512 -> xh[m][k-512]
// Stage: A | B, each 128 rows x 128B, chunk-XOR swizzled.
// Epilogue: bias + activation -> planar fp16 g_z16/g_f16/g_o16.
// ---------------------------------------------------------------------------
#define T_A  0
#define T_B  16384
#define STAGE_BYTES 32768
#define GEMM_SMEM (3 * STAGE_BYTES)     // 96KB -> 2 CTAs/SM

__global__ __launch_bounds__(256, 2)
void gemm_mma(const float* __restrict__ bias) {
    extern __shared__ char smem[];
    const uint32_t sb = smem_u32(smem);
    const int tid = threadIdx.x;
    const int lane = tid & 31;
    const int wrp = tid >> 5;
    const int wm = wrp & 3;          // m-warp 0..3  (32 rows each)
    const int wn = wrp >> 2;         // n-warp 0..1  (64 cols each)
    const int n0 = blockIdx.x * 128;
    const int m0 = blockIdx.y * 128;

    float acc[2][8][4];
#pragma unroll
    for (int mt = 0; mt < 2; mt++)
#pragma unroll
        for (int nt = 0; nt < 8; nt++)
#pragma unroll
            for (int r = 0; r < 4; r++) acc[mt][nt][r] = 0.0f;

    // --- loader geometry: 2 threads/row, 4 16B-chunks each, 2 tiles ---
    const int lrow = tid >> 1;
    const int lc0 = (tid & 1) * 4;

    // --- ldmatrix address components ---
    const int xorv = lane & 7;
    const int hvA = lane >> 4;
    const int hvB = (lane >> 3) & 1;
    uint32_t arow[2];
#pragma unroll
    for (int mt = 0; mt < 2; mt++)
        arow[mt] = (uint32_t)(wm * 32 + mt * 16 + (lane & 15)) * 128;
    uint32_t brow[4];
#pragma unroll
    for (int g2 = 0; g2 < 4; g2++)
        brow[g2] = (uint32_t)(wn * 64 + g2 * 16 + (lane & 7) + ((lane >> 4) & 1) * 8) * 128;

    auto load_stage = [&](int kc, int buf) {
        const uint32_t base = sb + buf * STAGE_BYTES;
        const int tap = kc >> 3;
        const int kb = (kc & 7) * 64;
        const int m = m0 + lrow;
        const bool ok = (tap == 1) || ((m & (Sq - 1)) != 0);
        const size_t amrow = (size_t)(ok && tap == 0 ? m - 1 : m) * Dq + kb;
        const int asz = ok ? 16 : 0;
        const size_t brow_g = (size_t)(n0 + lrow) * Kq + kc * 64;
#pragma unroll
        for (int c = lc0; c < lc0 + 4; c++) {
            const uint32_t dsto = (uint32_t)lrow * 128 +
                                  (uint32_t)((c ^ (lrow & 7)) * 16);
            cp16(base + T_A + dsto, g_xh + amrow + c * 8, asz);
            cp16(base + T_B + dsto, g_wh + brow_g + c * 8, 16);
        }
        CP_COMMIT();
    };

    load_stage(0, 0);
    load_stage(1, 1);

    int buf = 0, nbuf2 = 2;   // buf = kc%3 ; nbuf2 = (kc+2)%3

    for (int kc = 0; kc < 16; kc++) {
        const uint32_t base = sb + buf * STAGE_BYTES;

        if (kc < 15) { CP_WAIT(1); } else { CP_WAIT(0); }
        // Single barrier: (a) stage kc visible to all warps, (b) all warps
        // finished computing kc-1, so buffer (kc+2)%3 == (kc-1)%3 is free.
        __syncthreads();

        if (kc + 2 < 16) load_stage(kc + 2, nbuf2);

        // ---- compute: 4 k16 steps, 16 independent accumulators each ----
#pragma unroll
        for (int s = 0; s < 4; s++) {
            const uint32_t achunk = (uint32_t)(((s * 2 + hvA) ^ xorv) * 16);
            const uint32_t bchunk = (uint32_t)(((s * 2 + hvB) ^ xorv) * 16);

            uint32_t ah[2][4];
#pragma unroll
            for (int mt = 0; mt < 2; mt++)
                ldsm_x4(ah[mt][0], ah[mt][1], ah[mt][2], ah[mt][3],
                        base + T_A + arow[mt] + achunk);
            uint32_t bh[8][2];
#pragma unroll
            for (int g2 = 0; g2 < 4; g2++)
                ldsm_x4(bh[g2 * 2][0], bh[g2 * 2][1], bh[g2 * 2 + 1][0], bh[g2 * 2 + 1][1],
                        base + T_B + brow[g2] + bchunk);
#pragma unroll
            for (int mt = 0; mt < 2; mt++)
#pragma unroll
                for (int nt = 0; nt < 8; nt++)
                    mma_f16(acc[mt][nt][0], acc[mt][nt][1], acc[mt][nt][2], acc[mt][nt][3],
                            ah[mt][0], ah[mt][1], ah[mt][2], ah[mt][3],
                            bh[nt][0], bh[nt][1]);
        }

        buf = (buf == 2) ? 0 : buf + 1;
        nbuf2 = (nbuf2 == 2) ? 0 : nbuf2 + 1;
    }

    // ---- epilogue: bias + activation -> planar fp16 g_z16/g_f16/g_o16 ----
    const int sec = n0 >> 9;                 // 0=Z(tanh) 1=F(sig) 2=O(sig)
    __half* dst = (sec == 0) ? g_z16 : ((sec == 1) ? g_f16 : g_o16);
    const int colsec = (n0 & 511) + wn * 64;
    const int g = lane >> 2;
    const int tg = lane & 3;

#pragma unroll
    for (int mt = 0; mt < 2; mt++) {
        const int row0 = m0 + wm * 32 + mt * 16 + g;
#pragma unroll
        for (int nt = 0; nt < 8; nt++) {
            const int col = colsec + nt * 8 + tg * 2;
            const float b0 = bias[n0 + wn * 64 + nt * 8 + tg * 2];
            const float b1 = bias[n0 + wn * 64 + nt * 8 + tg * 2 + 1];
            float v0 = acc[mt][nt][0] + b0;
            float v1 = acc[mt][nt][1] + b1;
            float v2 = acc[mt][nt][2] + b0;
            float v3 = acc[mt][nt][3] + b1;
            if (sec == 0) {
                v0 = tanhf(v0); v1 = tanhf(v1); v2 = tanhf(v2); v3 = tanhf(v3);
            } else {
                v0 = 1.0f / (1.0f + __expf(-v0));
                v1 = 1.0f / (1.0f + __expf(-v1));
                v2 = 1.0f / (1.0f + __expf(-v2));
                v3 = 1.0f / (1.0f + __expf(-v3));
            }
            *reinterpret_cast<__half2*>(&dst[(size_t)row0 * Hq + col]) =
                __floats2half2_rn(v0, v1);
            *reinterpret_cast<__half2*>(&dst[(size_t)(row0 + 8) * Hq + col]) =
                __floats2half2_rn(v2, v3);
        }
    }
}

// ---------------------------------------------------------------------------
// Kernel 3: scan phase A — per-(chain-pair, chunk) affine summary (P, r).
// NC=64 -> 262144 threads, 2 chains (adjacent h) per thread via half2 loads.
// ---------------------------------------------------------------------------
__global__ void scanA_kernel() {
    const int gid = blockIdx.x * blockDim.x + threadIdx.x;
    if (gid >= (CH / 2) * NC) return;
    const int hp = gid & 255;                // h-pair index: h = 2hp, 2hp+1
    const int j = (gid >> 8) & (NC - 1);
    const int b = gid >> 14;                 // gid / (256 * 64)

    const __half2* z2 = reinterpret_cast<const __half2*>(g_z16);
    const __half2* f2 = reinterpret_cast<const __half2*>(g_f16);
    size_t hidx = (((size_t)b * Sq + j * ST) * Hq + hp * 2) >> 1;

    float2 P = make_float2(1.0f, 1.0f);
    float2 r = make_float2(0.0f, 0.0f);
#pragma unroll 4
    for (int t = 0; t < ST; t++, hidx += Hq / 2) {
        const float2 z = __half22float2(z2[hidx]);
        const float2 f = __half22float2(f2[hidx]);
        r.x = fmaf(f.x, r.x - z.x, z.x);
        r.y = fmaf(f.y, r.y - z.y, z.y);
        P.x *= f.x;
        P.y *= f.y;
    }
    const int chain2 = b * Hq + hp * 2;
    *reinterpret_cast<float2*>(&g_P[j * CH + chain2]) = P;
    *reinterpret_cast<float2*>(&g_r[j * CH + chain2]) = r;
}

// ---------------------------------------------------------------------------
// Kernel 4: scan phase B — fold upstream summaries, replay local recurrence.
// 2 chains per thread, NC=64. out = [C (B,S,H)] | [Hout (B,S,H)], fp32.
// ---------------------------------------------------------------------------
__global__ void scanB_kernel(float* __restrict__ out) {
    const int gid = blockIdx.x * blockDim.x + threadIdx.x;
    if (gid >= (CH / 2) * NC) return;
    const int hp = gid & 255;
    const int j = (gid >> 8) & (NC - 1);
    const int b = gid >> 14;
    const int chain2 = b * Hq + hp * 2;

    float2 c = make_float2(0.0f, 0.0f);
    for (int jj = 0; jj < j; jj++) {
        const float2 P = *reinterpret_cast<const float2*>(&g_P[jj * CH + chain2]);
        const float2 r = *reinterpret_cast<const float2*>(&g_r[jj * CH + chain2]);
        c.x = fmaf(P.x, c.x, r.x);
        c.y = fmaf(P.y, c.y, r.y);
    }

    const __half2* z2 = reinterpret_cast<const __half2*>(g_z16);
    const __half2* f2 = reinterpret_cast<const __half2*>(g_f16);
    const __half2* o2 = reinterpret_cast<const __half2*>(g_o16);
    float* Cout = out;
    float* Hout = out + (size_t)Mq * Hq;

    size_t idx = ((size_t)b * Sq + j * ST) * Hq + hp * 2;   // fp32 elem index
#pragma unroll 4
    for (int t = 0; t < ST; t++, idx += Hq) {
        const float2 z = __half22float2(z2[idx >> 1]);
        const float2 f = __half22float2(f2[idx >> 1]);
        const float2 o = __half22float2(o2[idx >> 1]);
        c.x = fmaf(f.x, c.x - z.x, z.x);
        c.y = fmaf(f.y, c.y - z.y, z.y);
        *reinterpret_cast<float2*>(&Cout[idx]) = c;
        *reinterpret_cast<float2*>(&Hout[idx]) = make_float2(o.x * c.x, o.y * c.y);
    }
}

// ---------------------------------------------------------------------------
// Launch
// ---------------------------------------------------------------------------
extern "C" void kernel_launch(void* const* d_in, const int* in_sizes, int n_in,
                              void* d_out, int out_size) {
    const float* x      = (const float*)d_in[0];  // [B, S, D]
    const float* conv_w = (const float*)d_in[1];  // [3H, D, 2]
    const float* conv_b = (const float*)d_in[2];  // [3H]
    float* out = (float*)d_out;                   // [C | Hout]
    (void)in_sizes; (void)n_in; (void)out_size;

    prep_fused<<<XPREP_BLOCKS + WPREP_BLOCKS, 256>>>(x, conv_w);

    cudaFuncSetAttribute(gemm_mma, cudaFuncAttributeMaxDynamicSharedMemorySize,
                         GEMM_SMEM);
    {
        dim3 grid(Nq / 128, Mq / 128);   // (12, 256); n fastest -> A L2 reuse
        gemm_mma<<<grid, 256, GEMM_SMEM>>>(conv_b);
    }

    scanA_kernel<<<(CH / 2) * NC / 256, 256>>>();
    scanB_kernel<<<(CH / 2) * NC / 256, 256>>>(out);
}